// round 8
// baseline (speedup 1.0000x reference)
#include <cuda_runtime.h>
#include <math_constants.h>

#define NPTS 4096
#define HALF (NPTS / 2)                       // 2048 points per half-scan
#define ROWS_PER_BLOCK 14
#define WARPS_PER_BLOCK (ROWS_PER_BLOCK * 2)  // 28 warps: 2 per row
#define NTHREADS (WARPS_PER_BLOCK * 32)       // 896
#define NBLOCKS ((NPTS + ROWS_PER_BLOCK - 1) / ROWS_PER_BLOCK)   // 293
#define FULL 0xffffffffu

__device__ __forceinline__ bool pless(float da, int ia, float db, int ib) {
    return (da < db) || (da == db && ia < ib);
}
#define CAS(dx, ix, dy, iy)                                  \
    do { if (!pless(dx, ix, dy, iy)) {                       \
        float _t = dx; dx = dy; dy = _t;                     \
        int _u = ix; ix = iy; iy = _u; } } while (0)

__device__ __forceinline__ void ins4(float dv, int j,
                                     float& d0, float& d1, float& d2, float& d3,
                                     int& i0, int& i1, int& i2, int& i3) {
    // calls arrive in strictly increasing j; strict '<' keeps top_k tie order
    d3 = dv; i3 = j;
    if (d3 < d2) { float t=d3; d3=d2; d2=t; int u=i3; i3=i2; i2=u; }
    if (d2 < d1) { float t=d2; d2=d1; d1=t; int u=i2; i2=i1; i1=u; }
    if (d1 < d0) { float t=d1; d1=d0; d0=t; int u=i1; i1=i0; i0=u; }
}

__global__ void __launch_bounds__(NTHREADS, 2)
nn_tag_pool_kernel(const float2* __restrict__ obs1,
                   const float2* __restrict__ obs2,
                   const float*  __restrict__ W,
                   const float*  __restrict__ bias,
                   float* __restrict__ out)
{
    __shared__ __align__(16) float sx[NPTS];
    __shared__ __align__(16) float sy[NPTS];
    __shared__ __align__(16) float4 sd[ROWS_PER_BLOCK][2];   // published dists
    __shared__ __align__(16) int4   si[ROWS_PER_BLOCK][2];   // published indices

    const int tid = threadIdx.x;
    {   // stage + deinterleave: obs2 AoS float2 -> SoA sx/sy
        const float4* g4 = (const float4*)obs2;
        for (int m = tid; m < NPTS / 2; m += NTHREADS) {
            float4 v = g4[m];                 // {x0,y0,x1,y1}
            sx[2*m]   = v.x;  sy[2*m]   = v.y;
            sx[2*m+1] = v.z;  sy[2*m+1] = v.w;
        }
    }
    __syncthreads();

    const int warp  = tid >> 5;
    const int lane  = tid & 31;
    const int rloc  = warp >> 1;              // row within block
    const int half  = warp & 1;               // which half of the scan
    const int i = blockIdx.x * ROWS_PER_BLOCK + rloc;   // query row
    if (i >= NPTS) return;                    // whole tail warps (last block only)

    const float qx = sx[i], qy = sy[i];

    const float4* sx4 = (const float4*)sx;
    const float4* sy4 = (const float4*)sy;
    const int vbase = half * (HALF / 4);      // float4 base of this half

    // ---------- seed: exact top-4 of this half's first 128 points ----------
    float d0, d1, d2, d3;
    int   i0, i1, i2, i3;
    {
        float4 X = sx4[vbase + lane];
        float4 Y = sy4[vbase + lane];
        const int jb = half * HALF + 4 * lane;

        float dxa = X.x - qx, dya = Y.x - qy;
        float dxb = X.y - qx, dyb = Y.y - qy;
        float dxc = X.z - qx, dyc = Y.z - qy;
        float dxd = X.w - qx, dyd = Y.w - qy;
        float e0 = fmaf(dxa, dxa, fmaf(dya, dya, 1.0f)); int a0 = jb + 0;
        float e1 = fmaf(dxb, dxb, fmaf(dyb, dyb, 1.0f)); int a1 = jb + 1;
        float e2 = fmaf(dxc, dxc, fmaf(dyc, dyc, 1.0f)); int a2 = jb + 2;
        float e3 = fmaf(dxd, dxd, fmaf(dyd, dyd, 1.0f)); int a3 = jb + 3;
        if (a0 == i) { e0 = CUDART_INF_F; a0 = 0x7fffffff; }
        if (a1 == i) { e1 = CUDART_INF_F; a1 = 0x7fffffff; }
        if (a2 == i) { e2 = CUDART_INF_F; a2 = 0x7fffffff; }
        if (a3 == i) { e3 = CUDART_INF_F; a3 = 0x7fffffff; }

        // sort 4 under (dist, idx) total order: 5-CAS network
        CAS(e0, a0, e2, a2); CAS(e1, a1, e3, a3);
        CAS(e0, a0, e1, a1); CAS(e2, a2, e3, a3);
        CAS(e1, a1, e2, a2);
        d0 = e0; d1 = e1; d2 = e2; d3 = e3;
        i0 = a0; i1 = a1; i2 = a2; i3 = a3;

        // butterfly merge: 32 sorted-4 -> warp-uniform sorted-4 (this half's prefix)
        #pragma unroll
        for (int off = 16; off >= 1; off >>= 1) {
            float f0 = __shfl_xor_sync(FULL, d0, off);
            float f1 = __shfl_xor_sync(FULL, d1, off);
            float f2 = __shfl_xor_sync(FULL, d2, off);
            float f3 = __shfl_xor_sync(FULL, d3, off);
            int   g0 = __shfl_xor_sync(FULL, i0, off);
            int   g1 = __shfl_xor_sync(FULL, i1, off);
            int   g2 = __shfl_xor_sync(FULL, i2, off);
            int   g3 = __shfl_xor_sync(FULL, i3, off);

            float m0, m1, m2, m3; int n0, n1, n2, n3;
            if (pless(d0, i0, f3, g3)) { m0 = d0; n0 = i0; } else { m0 = f3; n0 = g3; }
            if (pless(d1, i1, f2, g2)) { m1 = d1; n1 = i1; } else { m1 = f2; n1 = g2; }
            if (pless(d2, i2, f1, g1)) { m2 = d2; n2 = i2; } else { m2 = f1; n2 = g1; }
            if (pless(d3, i3, f0, g0)) { m3 = d3; n3 = i3; } else { m3 = f0; n3 = g0; }

            CAS(m0, n0, m2, n2); CAS(m1, n1, m3, n3);
            CAS(m0, n0, m1, n1); CAS(m2, n2, m3, n3);

            d0 = m0; d1 = m1; d2 = m2; d3 = m3;
            i0 = n0; i1 = n1; i2 = n2; i3 = n3;
        }
    }

    // ---------- main scan over this half: iters 1..15 ----------
    #pragma unroll 4
    for (int it = 1; it < HALF / 128; ++it) { // 4 pts/lane, 128 pts/warp/iter
        float4 X = sx4[vbase + it * 32 + lane];
        float4 Y = sy4[vbase + it * 32 + lane];

        float dxa = X.x - qx, dya = Y.x - qy;
        float dxb = X.y - qx, dyb = Y.y - qy;
        float dxc = X.z - qx, dyc = Y.z - qy;
        float dxd = X.w - qx, dyd = Y.w - qy;
        float v0 = fmaf(dxa, dxa, fmaf(dya, dya, 1.0f));
        float v1 = fmaf(dxb, dxb, fmaf(dyb, dyb, 1.0f));
        float v2 = fmaf(dxc, dxc, fmaf(dyc, dyc, 1.0f));
        float v3 = fmaf(dxd, dxd, fmaf(dyd, dyd, 1.0f));
        float mn = fminf(fminf(v0, v1), fminf(v2, v3));

        unsigned m = __ballot_sync(FULL, mn < d3);
        while (m) {                            // warp-uniform, rare
            int r = __ffs(m) - 1;
            m &= m - 1;
            float x0 = __shfl_sync(FULL, v0, r);
            float x1 = __shfl_sync(FULL, v1, r);
            float x2 = __shfl_sync(FULL, v2, r);
            float x3 = __shfl_sync(FULL, v3, r);
            int jb = half * HALF + (it * 32 + r) * 4;   // ascending within half

            if (jb + 0 != i && x0 < d3) ins4(x0, jb + 0, d0,d1,d2,d3, i0,i1,i2,i3);
            if (jb + 1 != i && x1 < d3) ins4(x1, jb + 1, d0,d1,d2,d3, i0,i1,i2,i3);
            if (jb + 2 != i && x2 < d3) ins4(x2, jb + 2, d0,d1,d2,d3, i0,i1,i2,i3);
            if (jb + 3 != i && x3 < d3) ins4(x3, jb + 3, d0,d1,d2,d3, i0,i1,i2,i3);

            if (m) m &= __ballot_sync(FULL, mn < d3);  // refilter vs tighter d3
        }
    }

    // ---------- publish per-half top-4, then cross-warp merge ----------
    if (lane == 0) {
        sd[rloc][half] = make_float4(d0, d1, d2, d3);
        si[rloc][half] = make_int4(i0, i1, i2, i3);
    }
    __syncthreads();
    if (half == 1) return;                    // odd warp done

    {   // merge partner's sorted-4 (disjoint halves; (d,idx) comparator => exact)
        float4 pe = sd[rloc][1];
        int4   pg = si[rloc][1];
        float f0 = pe.x, f1 = pe.y, f2 = pe.z, f3 = pe.w;
        int   g0 = pg.x, g1 = pg.y, g2 = pg.z, g3 = pg.w;

        float m0, m1, m2, m3; int n0, n1, n2, n3;
        if (pless(d0, i0, f3, g3)) { m0 = d0; n0 = i0; } else { m0 = f3; n0 = g3; }
        if (pless(d1, i1, f2, g2)) { m1 = d1; n1 = i1; } else { m1 = f2; n1 = g2; }
        if (pless(d2, i2, f1, g1)) { m2 = d2; n2 = i2; } else { m2 = f1; n2 = g1; }
        if (pless(d3, i3, f0, g0)) { m3 = d3; n3 = i3; } else { m3 = f0; n3 = g0; }

        CAS(m0, n0, m2, n2); CAS(m1, n1, m3, n3);
        CAS(m0, n0, m1, n1); CAS(m2, n2, m3, n3);

        i0 = n0; i1 = n1; i2 = n2; i3 = n3;
    }

    // ---------- epilogue: lane kk*8+o -> channel o of neighbor kk ----------
    const int o = lane & 7;
    const float w0 = W[o * 6 + 0];
    const float w1 = W[o * 6 + 1];
    const float w3 = W[o * 6 + 3];
    const float w4 = W[o * 6 + 4];
    const float cb = W[o * 6 + 2] + W[o * 6 + 5] + bias[o];

    const int kk = lane >> 3;
    const int j = (kk == 0) ? i0 : (kk == 1) ? i1 : (kk == 2) ? i2 : i3;

    const float pjx = sx[j], pjy = sy[j];
    const float2 a1j = obs1[j];
    const float2 a1i = obs1[i];

    const float px = pjx - qx;
    const float py = pjy - qy;
    const float vx = (pjx - a1j.x) - (qx - a1i.x);   // vel[j] - vel[i]
    const float vy = (pjy - a1j.y) - (qy - a1i.y);

    float r = fmaf(px, w0, fmaf(py, w1, fmaf(vx, w3, fmaf(vy, w4, cb))));
    out[i * 32 + lane] = fmaxf(r, 0.0f);
}

extern "C" void kernel_launch(void* const* d_in, const int* in_sizes, int n_in,
                              void* d_out, int out_size) {
    const float2* obs1 = (const float2*)d_in[0];
    const float2* obs2 = (const float2*)d_in[1];
    const float*  W    = (const float*)d_in[2];
    const float*  bias = (const float*)d_in[3];
    float* out = (float*)d_out;

    nn_tag_pool_kernel<<<NBLOCKS, NTHREADS>>>(obs1, obs2, W, bias, out);
}

// round 9
// speedup vs baseline: 1.3795x; 1.3795x over previous
#include <cuda_runtime.h>
#include <math_constants.h>

#define NPTS 4096
#define WARPS_PER_BLOCK 28
#define NTHREADS (WARPS_PER_BLOCK * 32)      // 896
#define NBLOCKS 147                           // 147*28 = 4116 >= 4096, 1 block/SM
#define FULL 0xffffffffu

// value-only compare-and-swap (ascending): 2 instr, no predicates
#define CASV(a, b) do { float _lo = fminf(a, b), _hi = fmaxf(a, b); a = _lo; b = _hi; } while (0)

__device__ __forceinline__ void ins4(float dv, int j,
                                     float& d0, float& d1, float& d2, float& d3,
                                     int& i0, int& i1, int& i2, int& i3) {
    // calls arrive in strictly increasing j; strict '<' keeps top_k tie order
    d3 = dv; i3 = j;
    if (d3 < d2) { float t=d3; d3=d2; d2=t; int u=i3; i3=i2; i2=u; }
    if (d2 < d1) { float t=d2; d2=d1; d1=t; int u=i2; i2=i1; i1=u; }
    if (d1 < d0) { float t=d1; d1=d0; d0=t; int u=i1; i1=i0; i0=u; }
}

__global__ void __launch_bounds__(NTHREADS)
nn_tag_pool_kernel(const float2* __restrict__ obs1,
                   const float2* __restrict__ obs2,
                   const float*  __restrict__ W,
                   const float*  __restrict__ bias,
                   float* __restrict__ out)
{
    __shared__ __align__(16) float sx[NPTS];
    __shared__ __align__(16) float sy[NPTS];

    const int tid = threadIdx.x;
    {   // stage + deinterleave: obs2 AoS float2 -> SoA sx/sy
        const float4* g4 = (const float4*)obs2;
        for (int m = tid; m < NPTS / 2; m += NTHREADS) {
            float4 v = g4[m];                 // {x0,y0,x1,y1}
            sx[2*m]   = v.x;  sy[2*m]   = v.y;
            sx[2*m+1] = v.z;  sy[2*m+1] = v.w;
        }
    }
    __syncthreads();

    const int warp = tid >> 5;
    const int lane = tid & 31;
    const int i = blockIdx.x * WARPS_PER_BLOCK + warp;   // query row
    if (i >= NPTS) return;                    // whole tail warps only

    const float qx = sx[i], qy = sy[i];

    const float4* sx4 = (const float4*)sx;
    const float4* sy4 = (const float4*)sy;

    // ---------- seed: exact 4th-smallest DISTANCE VALUE of points [0,128) ----
    float tau;
    {
        float4 X = sx4[lane];
        float4 Y = sy4[lane];
        const int jb = 4 * lane;

        float dxa = X.x - qx, dya = Y.x - qy;
        float dxb = X.y - qx, dyb = Y.y - qy;
        float dxc = X.z - qx, dyc = Y.z - qy;
        float dxd = X.w - qx, dyd = Y.w - qy;
        float e0 = fmaf(dxa, dxa, fmaf(dya, dya, 1.0f));
        float e1 = fmaf(dxb, dxb, fmaf(dyb, dyb, 1.0f));
        float e2 = fmaf(dxc, dxc, fmaf(dyc, dyc, 1.0f));
        float e3 = fmaf(dxd, dxd, fmaf(dyd, dyd, 1.0f));
        if (jb + 0 == i) e0 = CUDART_INF_F;   // exclude self
        if (jb + 1 == i) e1 = CUDART_INF_F;
        if (jb + 2 == i) e2 = CUDART_INF_F;
        if (jb + 3 == i) e3 = CUDART_INF_F;

        // sort 4 values: 5 CASV
        CASV(e0, e2); CASV(e1, e3); CASV(e0, e1); CASV(e2, e3); CASV(e1, e2);

        // values-only butterfly merge: 32 sorted-4 -> warp-uniform sorted-4
        #pragma unroll
        for (int off = 16; off >= 1; off >>= 1) {
            float f0 = __shfl_xor_sync(FULL, e0, off);
            float f1 = __shfl_xor_sync(FULL, e1, off);
            float f2 = __shfl_xor_sync(FULL, e2, off);
            float f3 = __shfl_xor_sync(FULL, e3, off);
            float m0 = fminf(e0, f3);
            float m1 = fminf(e1, f2);
            float m2 = fminf(e2, f1);
            float m3 = fminf(e3, f0);
            CASV(m0, m2); CASV(m1, m3); CASV(m0, m1); CASV(m2, m3);
            e0 = m0; e1 = m1; e2 = m2; e3 = m3;
        }
        tau = e3;   // exact 4th smallest of prefix (upper bound on global 4th)
    }

    // ---------- full scan with empty list, threshold min(tau, d3) ----------
    float d0 = CUDART_INF_F, d1 = CUDART_INF_F, d2 = CUDART_INF_F, d3 = CUDART_INF_F;
    int   i0 = 0, i1 = 0, i2 = 0, i3 = 0;

    for (int s = 0; s < NPTS / 512; ++s) {    // 8 superiters, 16 pts/lane
        const int b4 = s * 128 + lane;        // float4 base for this superiter
        float v[16];
        float mg0, mg1, mg2, mg3;

        #pragma unroll
        for (int g = 0; g < 4; ++g) {
            float4 X = sx4[b4 + g * 32];
            float4 Y = sy4[b4 + g * 32];
            float dxa = X.x - qx, dya = Y.x - qy;
            float dxb = X.y - qx, dyb = Y.y - qy;
            float dxc = X.z - qx, dyc = Y.z - qy;
            float dxd = X.w - qx, dyd = Y.w - qy;
            v[g*4+0] = fmaf(dxa, dxa, fmaf(dya, dya, 1.0f));
            v[g*4+1] = fmaf(dxb, dxb, fmaf(dyb, dyb, 1.0f));
            v[g*4+2] = fmaf(dxc, dxc, fmaf(dyc, dyc, 1.0f));
            v[g*4+3] = fmaf(dxd, dxd, fmaf(dyd, dyd, 1.0f));
            float m = fminf(fminf(v[g*4+0], v[g*4+1]), fminf(v[g*4+2], v[g*4+3]));
            if (g == 0) mg0 = m; else if (g == 1) mg1 = m;
            else if (g == 2) mg2 = m; else mg3 = m;
        }

        float t = fminf(tau, d3);
        float mall = fminf(fminf(mg0, mg1), fminf(mg2, mg3));

        // ONE ballot + ONE branch per 512 points
        if (__ballot_sync(FULL, mall <= t)) {
            // rare path: per-group ballots, ascending j throughout
            #pragma unroll
            for (int g = 0; g < 4; ++g) {
                float mg = (g == 0) ? mg0 : (g == 1) ? mg1 : (g == 2) ? mg2 : mg3;
                unsigned mk = __ballot_sync(FULL, mg <= t);
                while (mk) {                   // warp-uniform
                    int r = __ffs(mk) - 1;
                    mk &= mk - 1;
                    float x0 = __shfl_sync(FULL, v[g*4+0], r);
                    float x1 = __shfl_sync(FULL, v[g*4+1], r);
                    float x2 = __shfl_sync(FULL, v[g*4+2], r);
                    float x3 = __shfl_sync(FULL, v[g*4+3], r);
                    int jb = s * 512 + g * 128 + 4 * r;   // ascending

                    if (jb + 0 != i && x0 < d3) ins4(x0, jb + 0, d0,d1,d2,d3, i0,i1,i2,i3);
                    if (jb + 1 != i && x1 < d3) ins4(x1, jb + 1, d0,d1,d2,d3, i0,i1,i2,i3);
                    if (jb + 2 != i && x2 < d3) ins4(x2, jb + 2, d0,d1,d2,d3, i0,i1,i2,i3);
                    if (jb + 3 != i && x3 < d3) ins4(x3, jb + 3, d0,d1,d2,d3, i0,i1,i2,i3);

                    t = fminf(tau, d3);
                    if (mk) mk &= __ballot_sync(FULL, mg <= t);   // refilter
                }
            }
        }
    }

    // ---------- epilogue: lane kk*8+o -> channel o of neighbor kk ----------
    const int o = lane & 7;
    const float w0 = W[o * 6 + 0];
    const float w1 = W[o * 6 + 1];
    const float w3 = W[o * 6 + 3];
    const float w4 = W[o * 6 + 4];
    const float cb = W[o * 6 + 2] + W[o * 6 + 5] + bias[o];

    const int kk = lane >> 3;
    const int j = (kk == 0) ? i0 : (kk == 1) ? i1 : (kk == 2) ? i2 : i3;

    const float pjx = sx[j], pjy = sy[j];
    const float2 a1j = obs1[j];
    const float2 a1i = obs1[i];

    const float px = pjx - qx;
    const float py = pjy - qy;
    const float vx = (pjx - a1j.x) - (qx - a1i.x);   // vel[j] - vel[i]
    const float vy = (pjy - a1j.y) - (qy - a1i.y);

    float r = fmaf(px, w0, fmaf(py, w1, fmaf(vx, w3, fmaf(vy, w4, cb))));
    out[i * 32 + lane] = fmaxf(r, 0.0f);
}

extern "C" void kernel_launch(void* const* d_in, const int* in_sizes, int n_in,
                              void* d_out, int out_size) {
    const float2* obs1 = (const float2*)d_in[0];
    const float2* obs2 = (const float2*)d_in[1];
    const float*  W    = (const float*)d_in[2];
    const float*  bias = (const float*)d_in[3];
    float* out = (float*)d_out;

    nn_tag_pool_kernel<<<NBLOCKS, NTHREADS>>>(obs1, obs2, W, bias, out);
}